// round 1
// baseline (speedup 1.0000x reference)
#include <cuda_runtime.h>
#include <math.h>

#define BATCH 1024
#define DD 128
#define G3 384
#define TT 96
#define NSTEP 95
#define S_ODE 132
#define S_GRU 388

// scratch (device globals -- no allocation allowed)
__device__ __align__(256) float g_traj[(size_t)TT * BATCH * DD];
__device__ __align__(256) float g_gi[(size_t)TT * BATCH * G3];
__device__ __align__(256) float g_h1[(size_t)TT * BATCH * DD];
__device__ __align__(256) float g_h2[(size_t)BATCH * DD];

__device__ __forceinline__ float sigm(float x) { return 1.0f / (1.0f + expf(-x)); }

// ---------------------------------------------------------------------------
// Phase 1: Dopri5 ODE integration. One warp handles 2 batch rows; lane l holds
// state elements 4l..4l+3. Matvec: out[j] = b[j] + sum_k y[k]*W[j][k], with
// W transposed in smem (Ws[k*S_ODE + j]).
// ---------------------------------------------------------------------------
__device__ __forceinline__ void ode_eval(const float (&a)[2][4], float (&o)[2][4],
                                         const float* __restrict__ Ws,
                                         const float (&bv)[4], int lane)
{
    float acc0[4], acc1[4];
#pragma unroll
    for (int m = 0; m < 4; m++) { acc0[m] = bv[m]; acc1[m] = bv[m]; }
#pragma unroll 8
    for (int kb = 0; kb < 32; kb++) {
#pragma unroll
        for (int mk = 0; mk < 4; mk++) {
            const int k = 4 * kb + mk;
            const float x0 = __shfl_sync(0xffffffffu, a[0][mk], kb);
            const float x1 = __shfl_sync(0xffffffffu, a[1][mk], kb);
            const float4 w = *(const float4*)(Ws + k * S_ODE + 4 * lane);
            acc0[0] = fmaf(x0, w.x, acc0[0]);
            acc0[1] = fmaf(x0, w.y, acc0[1]);
            acc0[2] = fmaf(x0, w.z, acc0[2]);
            acc0[3] = fmaf(x0, w.w, acc0[3]);
            acc1[0] = fmaf(x1, w.x, acc1[0]);
            acc1[1] = fmaf(x1, w.y, acc1[1]);
            acc1[2] = fmaf(x1, w.z, acc1[2]);
            acc1[3] = fmaf(x1, w.w, acc1[3]);
        }
    }
#pragma unroll
    for (int m = 0; m < 4; m++) { o[0][m] = tanhf(acc0[m]); o[1][m] = tanhf(acc1[m]); }
}

__global__ void __launch_bounds__(128)
ode_kernel(const float* __restrict__ yl, const float* __restrict__ yh,
           const float* __restrict__ W, const float* __restrict__ bias)
{
    extern __shared__ float sm[];
    const int tid = threadIdx.x;
    for (int idx = tid; idx < DD * DD; idx += 128) {
        const int j = idx >> 7, k = idx & 127;
        sm[k * S_ODE + j] = W[idx];
    }
    __syncthreads();

    const int lane = tid & 31, warp = tid >> 5;
    const int row0 = blockIdx.x * 8 + warp * 2;

    float bv[4];
#pragma unroll
    for (int m = 0; m < 4; m++) bv[m] = bias[4 * lane + m];

    float y[2][4];
#pragma unroll
    for (int r = 0; r < 2; r++) {
        const int row = row0 + r;
#pragma unroll
        for (int m = 0; m < 4; m++) {
            const int e = 4 * lane + m;
            y[r][m] = (e < 32) ? yl[row * 32 + e] : yh[row * 96 + (e - 32)];
        }
        *(float4*)(g_traj + (size_t)row * DD + 4 * lane) =
            make_float4(y[r][0], y[r][1], y[r][2], y[r][3]);
    }

    float k1[2][4], k2[2][4], k3[2][4], k4[2][4], k5[2][4], k6[2][4], ar[2][4];

    for (int st = 0; st < NSTEP; st++) {
        const float t0 = (float)st * (1.0f / 95.0f);
        const float t1 = (st == NSTEP - 1) ? 1.0f : (float)(st + 1) * (1.0f / 95.0f);
        const float dt = t1 - t0;

        ode_eval(y, k1, sm, bv, lane);

#pragma unroll
        for (int r = 0; r < 2; r++)
#pragma unroll
            for (int m = 0; m < 4; m++)
                ar[r][m] = y[r][m] + dt * (0.2f * k1[r][m]);
        ode_eval(ar, k2, sm, bv, lane);

#pragma unroll
        for (int r = 0; r < 2; r++)
#pragma unroll
            for (int m = 0; m < 4; m++) {
                float s = 0.075f * k1[r][m];
                s = fmaf(0.225f, k2[r][m], s);
                ar[r][m] = fmaf(dt, s, y[r][m]);
            }
        ode_eval(ar, k3, sm, bv, lane);

#pragma unroll
        for (int r = 0; r < 2; r++)
#pragma unroll
            for (int m = 0; m < 4; m++) {
                float s = 0.9777777777777777f * k1[r][m];
                s = fmaf(-3.7333333333333334f, k2[r][m], s);
                s = fmaf(3.5555555555555554f, k3[r][m], s);
                ar[r][m] = fmaf(dt, s, y[r][m]);
            }
        ode_eval(ar, k4, sm, bv, lane);

#pragma unroll
        for (int r = 0; r < 2; r++)
#pragma unroll
            for (int m = 0; m < 4; m++) {
                float s = 2.9525906892141633f * k1[r][m];
                s = fmaf(-11.595793324188385f, k2[r][m], s);
                s = fmaf(9.822892851699436f, k3[r][m], s);
                s = fmaf(-0.2908093278463649f, k4[r][m], s);
                ar[r][m] = fmaf(dt, s, y[r][m]);
            }
        ode_eval(ar, k5, sm, bv, lane);

#pragma unroll
        for (int r = 0; r < 2; r++)
#pragma unroll
            for (int m = 0; m < 4; m++) {
                float s = 2.8462752525252526f * k1[r][m];
                s = fmaf(-10.757575757575758f, k2[r][m], s);
                s = fmaf(8.906422717743473f, k3[r][m], s);
                s = fmaf(0.2784090909090909f, k4[r][m], s);
                s = fmaf(-0.2735313036020583f, k5[r][m], s);
                ar[r][m] = fmaf(dt, s, y[r][m]);
            }
        ode_eval(ar, k6, sm, bv, lane);

#pragma unroll
        for (int r = 0; r < 2; r++) {
#pragma unroll
            for (int m = 0; m < 4; m++) {
                float s = 0.09114583333333333f * k1[r][m];
                s = fmaf(0.44923629829290207f, k3[r][m], s);
                s = fmaf(0.6510416666666666f, k4[r][m], s);
                s = fmaf(-0.322376179245283f, k5[r][m], s);
                s = fmaf(0.13095238095238096f, k6[r][m], s);
                y[r][m] = fmaf(dt, s, y[r][m]);
            }
            *(float4*)(g_traj + ((size_t)(st + 1) * BATCH + row0 + r) * DD + 4 * lane) =
                make_float4(y[r][0], y[r][1], y[r][2], y[r][3]);
        }
    }
}

// ---------------------------------------------------------------------------
// Phase 2/4: gi = X @ W_ih^T + b_ih for all (t, row) items. Parallel GEMM.
// CTA handles 96 items (12 iters x 4 warps x 2 items), W transposed in smem.
// ---------------------------------------------------------------------------
__global__ void __launch_bounds__(128)
gi_kernel(const float* __restrict__ X, const float* __restrict__ Wih,
          const float* __restrict__ bih, float* __restrict__ gi)
{
    extern __shared__ float sm[];
    const int tid = threadIdx.x;
    for (int idx = tid; idx < G3 * DD; idx += 128) {
        const int j = idx >> 7, k = idx & 127;
        sm[k * S_GRU + j] = Wih[idx];
    }
    __syncthreads();

    const int lane = tid & 31, warp = tid >> 5;
    float bv[3][4];
#pragma unroll
    for (int g = 0; g < 3; g++)
#pragma unroll
        for (int m = 0; m < 4; m++) bv[g][m] = bih[128 * g + 4 * lane + m];

    for (int it = 0; it < 12; it++) {
        const int item = blockIdx.x * 96 + it * 8 + warp * 2;
        float a[2][4];
#pragma unroll
        for (int r = 0; r < 2; r++) {
            const float4 v = *(const float4*)(X + (size_t)(item + r) * DD + 4 * lane);
            a[r][0] = v.x; a[r][1] = v.y; a[r][2] = v.z; a[r][3] = v.w;
        }
        float acc[2][3][4];
#pragma unroll
        for (int r = 0; r < 2; r++)
#pragma unroll
            for (int g = 0; g < 3; g++)
#pragma unroll
                for (int m = 0; m < 4; m++) acc[r][g][m] = bv[g][m];

#pragma unroll 4
        for (int kb = 0; kb < 32; kb++) {
#pragma unroll
            for (int mk = 0; mk < 4; mk++) {
                const int k = 4 * kb + mk;
                const float x0 = __shfl_sync(0xffffffffu, a[0][mk], kb);
                const float x1 = __shfl_sync(0xffffffffu, a[1][mk], kb);
#pragma unroll
                for (int g = 0; g < 3; g++) {
                    const float4 w = *(const float4*)(sm + k * S_GRU + 128 * g + 4 * lane);
                    acc[0][g][0] = fmaf(x0, w.x, acc[0][g][0]);
                    acc[0][g][1] = fmaf(x0, w.y, acc[0][g][1]);
                    acc[0][g][2] = fmaf(x0, w.z, acc[0][g][2]);
                    acc[0][g][3] = fmaf(x0, w.w, acc[0][g][3]);
                    acc[1][g][0] = fmaf(x1, w.x, acc[1][g][0]);
                    acc[1][g][1] = fmaf(x1, w.y, acc[1][g][1]);
                    acc[1][g][2] = fmaf(x1, w.z, acc[1][g][2]);
                    acc[1][g][3] = fmaf(x1, w.w, acc[1][g][3]);
                }
            }
        }
#pragma unroll
        for (int r = 0; r < 2; r++)
#pragma unroll
            for (int g = 0; g < 3; g++)
                *(float4*)(gi + (size_t)(item + r) * G3 + 128 * g + 4 * lane) =
                    make_float4(acc[r][g][0], acc[r][g][1], acc[r][g][2], acc[r][g][3]);
    }
}

// ---------------------------------------------------------------------------
// Phase 3/5: GRU recurrent scan. Warp holds 2 rows' hidden state in registers.
// ---------------------------------------------------------------------------
__global__ void __launch_bounds__(128)
gru_kernel(const float* __restrict__ gi, const float* __restrict__ Whh,
           const float* __restrict__ bhh, float* __restrict__ otraj,
           float* __restrict__ olast)
{
    extern __shared__ float sm[];
    const int tid = threadIdx.x;
    for (int idx = tid; idx < G3 * DD; idx += 128) {
        const int j = idx >> 7, k = idx & 127;
        sm[k * S_GRU + j] = Whh[idx];
    }
    __syncthreads();

    const int lane = tid & 31, warp = tid >> 5;
    const int row0 = blockIdx.x * 8 + warp * 2;
    float bv[3][4];
#pragma unroll
    for (int g = 0; g < 3; g++)
#pragma unroll
        for (int m = 0; m < 4; m++) bv[g][m] = bhh[128 * g + 4 * lane + m];

    float h[2][4];
#pragma unroll
    for (int r = 0; r < 2; r++)
#pragma unroll
        for (int m = 0; m < 4; m++) h[r][m] = 0.0f;

    for (int t = 0; t < TT; t++) {
        float acc[2][3][4];
#pragma unroll
        for (int r = 0; r < 2; r++)
#pragma unroll
            for (int g = 0; g < 3; g++)
#pragma unroll
                for (int m = 0; m < 4; m++) acc[r][g][m] = bv[g][m];

#pragma unroll 4
        for (int kb = 0; kb < 32; kb++) {
#pragma unroll
            for (int mk = 0; mk < 4; mk++) {
                const int k = 4 * kb + mk;
                const float x0 = __shfl_sync(0xffffffffu, h[0][mk], kb);
                const float x1 = __shfl_sync(0xffffffffu, h[1][mk], kb);
#pragma unroll
                for (int g = 0; g < 3; g++) {
                    const float4 w = *(const float4*)(sm + k * S_GRU + 128 * g + 4 * lane);
                    acc[0][g][0] = fmaf(x0, w.x, acc[0][g][0]);
                    acc[0][g][1] = fmaf(x0, w.y, acc[0][g][1]);
                    acc[0][g][2] = fmaf(x0, w.z, acc[0][g][2]);
                    acc[0][g][3] = fmaf(x0, w.w, acc[0][g][3]);
                    acc[1][g][0] = fmaf(x1, w.x, acc[1][g][0]);
                    acc[1][g][1] = fmaf(x1, w.y, acc[1][g][1]);
                    acc[1][g][2] = fmaf(x1, w.z, acc[1][g][2]);
                    acc[1][g][3] = fmaf(x1, w.w, acc[1][g][3]);
                }
            }
        }

#pragma unroll
        for (int r = 0; r < 2; r++) {
            const float* gp = gi + ((size_t)t * BATCH + row0 + r) * G3 + 4 * lane;
            const float4 vr = *(const float4*)(gp);
            const float4 vz = *(const float4*)(gp + 128);
            const float4 vn = *(const float4*)(gp + 256);
            const float ir[4] = {vr.x, vr.y, vr.z, vr.w};
            const float iz[4] = {vz.x, vz.y, vz.z, vz.w};
            const float inn[4] = {vn.x, vn.y, vn.z, vn.w};
#pragma unroll
            for (int m = 0; m < 4; m++) {
                const float rg = sigm(ir[m] + acc[r][0][m]);
                const float zg = sigm(iz[m] + acc[r][1][m]);
                const float ng = tanhf(inn[m] + rg * acc[r][2][m]);
                h[r][m] = (1.0f - zg) * ng + zg * h[r][m];
            }
        }
        if (otraj) {
#pragma unroll
            for (int r = 0; r < 2; r++)
                *(float4*)(otraj + ((size_t)t * BATCH + row0 + r) * DD + 4 * lane) =
                    make_float4(h[r][0], h[r][1], h[r][2], h[r][3]);
        }
    }
    if (olast) {
#pragma unroll
        for (int r = 0; r < 2; r++)
            *(float4*)(olast + (size_t)(row0 + r) * DD + 4 * lane) =
                make_float4(h[r][0], h[r][1], h[r][2], h[r][3]);
    }
}

// ---------------------------------------------------------------------------
// Phase 6: FC head. hidden = gelu_exact(h2 @ W1^T + b1); pred = hidden @ W2^T + b2.
// Block: 8 rows, 256 threads. W tiles transposed in smem with padding.
// ---------------------------------------------------------------------------
__global__ void __launch_bounds__(256)
fc_kernel(const float* __restrict__ W1, const float* __restrict__ b1,
          const float* __restrict__ W2, const float* __restrict__ b2,
          float* __restrict__ out)
{
    extern __shared__ float sm[];
    float* hs = sm;          // 8*128
    float* hd = sm + 1024;   // 8*64
    float* wt = sm + 1536;   // max(128*68, 64*260) = 16640
    const int tid = threadIdx.x;
    const int row0 = blockIdx.x * 8;

    for (int idx = tid; idx < 8 * DD; idx += 256) hs[idx] = g_h2[(size_t)row0 * DD + idx];
    for (int idx = tid; idx < 64 * DD; idx += 256) {
        const int j = idx >> 7, k = idx & 127;
        wt[k * 68 + j] = W1[idx];
    }
    __syncthreads();

#pragma unroll
    for (int i = 0; i < 2; i++) {
        const int p = tid + 256 * i, r = p >> 6, j = p & 63;
        float acc = b1[j];
#pragma unroll 8
        for (int k = 0; k < DD; k++) acc = fmaf(hs[r * DD + k], wt[k * 68 + j], acc);
        hd[r * 64 + j] = acc * normcdff(acc);
    }

    for (int c = 0; c < 12; c++) {
        __syncthreads();
        for (int idx = tid; idx < 256 * 64; idx += 256) {
            const int jj = idx >> 6, k = idx & 63;
            wt[k * 260 + jj] = W2[(size_t)(c * 256 + jj) * 64 + k];
        }
        __syncthreads();
        const int j = c * 256 + tid;
        float acc[8];
#pragma unroll
        for (int r = 0; r < 8; r++) acc[r] = b2[j];
#pragma unroll 8
        for (int k = 0; k < 64; k++) {
            const float w = wt[k * 260 + tid];
#pragma unroll
            for (int r = 0; r < 8; r++) acc[r] = fmaf(hd[r * 64 + k], w, acc[r]);
        }
#pragma unroll
        for (int r = 0; r < 8; r++) out[(size_t)(row0 + r) * 3072 + j] = acc[r];
    }
}

// ---------------------------------------------------------------------------
extern "C" void kernel_launch(void* const* d_in, const int* in_sizes, int n_in,
                              void* d_out, int out_size)
{
    (void)in_sizes; (void)n_in; (void)out_size;
    // metadata order: x, yl, yh, W_ode, b_ode, W_ih0, W_hh0, b_ih0, b_hh0,
    //                 W_ih1, W_hh1, b_ih1, b_hh1, W1, b1, W2, b2
    const float* yl    = (const float*)d_in[1];
    const float* yh    = (const float*)d_in[2];
    const float* W_ode = (const float*)d_in[3];
    const float* b_ode = (const float*)d_in[4];
    const float* W_ih0 = (const float*)d_in[5];
    const float* W_hh0 = (const float*)d_in[6];
    const float* b_ih0 = (const float*)d_in[7];
    const float* b_hh0 = (const float*)d_in[8];
    const float* W_ih1 = (const float*)d_in[9];
    const float* W_hh1 = (const float*)d_in[10];
    const float* b_ih1 = (const float*)d_in[11];
    const float* b_hh1 = (const float*)d_in[12];
    const float* W1    = (const float*)d_in[13];
    const float* b1    = (const float*)d_in[14];
    const float* W2    = (const float*)d_in[15];
    const float* b2    = (const float*)d_in[16];
    float* out = (float*)d_out;

    float *traj, *gibuf, *h1, *h2;
    cudaGetSymbolAddress((void**)&traj,  g_traj);
    cudaGetSymbolAddress((void**)&gibuf, g_gi);
    cudaGetSymbolAddress((void**)&h1,    g_h1);
    cudaGetSymbolAddress((void**)&h2,    g_h2);

    const int SM_ODE = S_ODE * DD * 4;              // 67,584 B
    const int SM_GRU = S_GRU * DD * 4;              // 198,656 B
    const int SM_FC  = (1536 + 64 * 260) * 4;       // 72,704 B
    cudaFuncSetAttribute(ode_kernel, cudaFuncAttributeMaxDynamicSharedMemorySize, SM_ODE);
    cudaFuncSetAttribute(gi_kernel,  cudaFuncAttributeMaxDynamicSharedMemorySize, SM_GRU);
    cudaFuncSetAttribute(gru_kernel, cudaFuncAttributeMaxDynamicSharedMemorySize, SM_GRU);
    cudaFuncSetAttribute(fc_kernel,  cudaFuncAttributeMaxDynamicSharedMemorySize, SM_FC);

    ode_kernel<<<128, 128, SM_ODE>>>(yl, yh, W_ode, b_ode);
    gi_kernel <<<1024, 128, SM_GRU>>>(traj, W_ih0, b_ih0, gibuf);
    gru_kernel<<<128, 128, SM_GRU>>>(gibuf, W_hh0, b_hh0, h1, nullptr);
    gi_kernel <<<1024, 128, SM_GRU>>>(h1, W_ih1, b_ih1, gibuf);
    gru_kernel<<<128, 128, SM_GRU>>>(gibuf, W_hh1, b_hh1, nullptr, h2);
    fc_kernel <<<128, 256, SM_FC>>>(W1, b1, W2, b2, out);
}